// round 9
// baseline (speedup 1.0000x reference)
#include <cuda_runtime.h>
#include <cuda_fp16.h>

// C3 sparse-connectivity conv via fp16 mma.sync (f32 accum), k16 tap-pairing
// + ldmatrix fragment loads.
// x: [32,6,512,512] f32, weight: [16,6,5,5] f32, bias: [16] f32
// out: [32,16,508,508] f32
//
// Per output row r, ky:  D[128px,16oc] += A*B with K packed as
//   pairs (kx=0,1), (kx=2,3) -> m16n8k16 ; kx=4 -> m16n8k8.
// A = shifted views into a channels-last fp16 patch (16 B/pixel); all A
// fragments loaded with ldmatrix.x4 (one instr = full 4-reg fragment).
// CTA = 128 px * 8 output rows * 16 oc, one batch image. Warp = one row.

#define OW 508
#define OH 508
#define IW 512
#define IH 512
#define TW 128
#define TH 8
#define PW 132
#define PH 12
#define PLANE (IH * IW)

// smem layout (bytes)
#define SA     0                       // patch [PH][PW] x 16B = 25344
#define SB16   25344                   // [ky][p][half][n][t] uint2 = 5*2*2*32*8 = 6400
#define SBT    31744                   // [ky][half][n][t] u32   = 5*2*32*4 = 1280
#define SBIAS  33024                   // 16 f32
#define SMEM_TOTAL 33088

__constant__ unsigned CONN[16] = {
    0x07, 0x0E, 0x1C, 0x38, 0x31, 0x23, 0x0F, 0x1E,
    0x3C, 0x39, 0x33, 0x27, 0x1B, 0x36, 0x2D, 0x3F};

__device__ __forceinline__ unsigned pack_h2(float a, float b) {
    __half2 h = __floats2half2_rn(a, b);
    return *reinterpret_cast<unsigned*>(&h);
}
__device__ __forceinline__ unsigned smem_u32(const void* p) {
    unsigned a;
    asm("{ .reg .u64 t; cvta.to.shared.u64 t, %1; cvt.u32.u64 %0, t; }"
        : "=r"(a) : "l"(p));
    return a;
}
__device__ __forceinline__ void ldsm4(unsigned addr, unsigned& r0, unsigned& r1,
                                      unsigned& r2, unsigned& r3) {
    asm volatile("ldmatrix.sync.aligned.m8n8.x4.shared.b16 {%0,%1,%2,%3}, [%4];"
                 : "=r"(r0), "=r"(r1), "=r"(r2), "=r"(r3) : "r"(addr));
}
__device__ __forceinline__ void mma16816(float* c, unsigned a0, unsigned a1,
                                         unsigned a2, unsigned a3,
                                         unsigned b0, unsigned b1) {
    asm volatile(
        "mma.sync.aligned.m16n8k16.row.col.f32.f16.f16.f32 "
        "{%0,%1,%2,%3}, {%4,%5,%6,%7}, {%8,%9}, {%0,%1,%2,%3};"
        : "+f"(c[0]), "+f"(c[1]), "+f"(c[2]), "+f"(c[3])
        : "r"(a0), "r"(a1), "r"(a2), "r"(a3), "r"(b0), "r"(b1));
}
__device__ __forceinline__ void mma16808(float* c, unsigned a0, unsigned a1,
                                         unsigned b0) {
    asm volatile(
        "mma.sync.aligned.m16n8k8.row.col.f32.f16.f16.f32 "
        "{%0,%1,%2,%3}, {%4,%5}, {%6}, {%0,%1,%2,%3};"
        : "+f"(c[0]), "+f"(c[1]), "+f"(c[2]), "+f"(c[3])
        : "r"(a0), "r"(a1), "r"(b0));
}

__global__ void __launch_bounds__(256, 2)
c3_hmma(const float* __restrict__ x,
        const float* __restrict__ wgt,
        const float* __restrict__ bias,
        float* __restrict__ out)
{
    __shared__ __align__(16) char smem[SMEM_TOTAL];

    const int tid = threadIdx.x;
    const int x0 = blockIdx.x * TW;
    const int y0 = blockIdx.y * TH;
    const int b  = blockIdx.z;

    // ---- channels-last fp16 patch ----
    const float* xb = x + (size_t)b * 6 * PLANE;
    for (int i = tid; i < PH * PW; i += 256) {
        int row = i / PW, col = i % PW;
        int gy = y0 + row, gx = x0 + col;
        uint4 v = make_uint4(0u, 0u, 0u, 0u);
        if (gy < IH && gx < IW) {
            const float* p = xb + (size_t)gy * IW + gx;
            v.x = pack_h2(p[0],         p[PLANE]);
            v.y = pack_h2(p[2 * PLANE], p[3 * PLANE]);
            v.z = pack_h2(p[4 * PLANE], p[5 * PLANE]);
        }
        *reinterpret_cast<uint4*>(smem + SA + i * 16) = v;
    }
    // ---- k16 B tiles: [ky][p][half][n][t] -> uint2 {tap 2p, tap 2p+1} ----
    for (int i = tid; i < 640; i += 256) {
        int t    = i & 3;
        int n    = (i >> 2) & 7;
        int half = (i >> 5) & 1;
        int p    = (i >> 6) & 1;
        int ky   = i >> 7;
        int oc = half * 8 + n;
        unsigned m = CONN[oc];
        uint2 w = make_uint2(0u, 0u);
        if (t < 3) {
            int ia = 2 * t, ib = 2 * t + 1;
            const float* wp = wgt + (oc * 6 * 5 + ky) * 5;
            float la = (m & (1u << ia)) ? wp[ia * 25 + 2 * p] : 0.f;
            float lb = (m & (1u << ib)) ? wp[ib * 25 + 2 * p] : 0.f;
            float ha = (m & (1u << ia)) ? wp[ia * 25 + 2 * p + 1] : 0.f;
            float hb = (m & (1u << ib)) ? wp[ib * 25 + 2 * p + 1] : 0.f;
            w.x = pack_h2(la, lb);
            w.y = pack_h2(ha, hb);
        }
        *reinterpret_cast<uint2*>(smem + SB16 + i * 8) = w;
    }
    // ---- tail (kx=4) B tiles: [ky][half][n][t] -> u32 ----
    for (int i = tid; i < 320; i += 256) {
        int t    = i & 3;
        int n    = (i >> 2) & 7;
        int half = (i >> 5) & 1;
        int ky   = i >> 6;
        int oc = half * 8 + n;
        unsigned m = CONN[oc];
        unsigned w = 0u;
        if (t < 3) {
            int ia = 2 * t, ib = 2 * t + 1;
            const float* wp = wgt + (oc * 6 * 5 + ky) * 5;
            float a = (m & (1u << ia)) ? wp[ia * 25 + 4] : 0.f;
            float c = (m & (1u << ib)) ? wp[ib * 25 + 4] : 0.f;
            w = pack_h2(a, c);
        }
        *reinterpret_cast<unsigned*>(smem + SBT + i * 4) = w;
    }
    if (tid < 16)
        reinterpret_cast<float*>(smem + SBIAS)[tid] = bias[tid];
    __syncthreads();

    const unsigned sbase = smem_u32(smem);
    const int wid  = tid >> 5;
    const int lane = tid & 31;
    const int t = lane & 3;
    const int r = wid;               // output row within tile
    const int j = lane & 7;
    const int q = lane >> 3;

    // per-thread ldmatrix pixel offsets (bytes)
    const unsigned poff16 = (unsigned)(j + (q & 1) * 8 + (q >> 1)) * 16;
    const unsigned poff8  = (unsigned)(j + (q & 1) * 8 + (q >> 1) * 16) * 16;

    float acc[8][2][4];
    {
        const float* bs = reinterpret_cast<const float*>(smem + SBIAS);
#pragma unroll
        for (int h = 0; h < 2; ++h) {
            float b0 = bs[h * 8 + 2 * t];
            float b1 = bs[h * 8 + 2 * t + 1];
#pragma unroll
            for (int m = 0; m < 8; ++m) {
                acc[m][h][0] = b0; acc[m][h][1] = b1;
                acc[m][h][2] = b0; acc[m][h][3] = b1;
            }
        }
    }

#pragma unroll 1
    for (int ky = 0; ky < 5; ++ky) {
        const unsigned rowb = sbase + SA + (unsigned)((r + ky) * PW) * 16;
#pragma unroll
        for (int p = 0; p < 2; ++p) {
            uint2 bh0 = *reinterpret_cast<const uint2*>(
                smem + SB16 + (((ky * 2 + p) * 2 + 0) * 32 + lane) * 8);
            uint2 bh1 = *reinterpret_cast<const uint2*>(
                smem + SB16 + (((ky * 2 + p) * 2 + 1) * 32 + lane) * 8);
            const unsigned abase = rowb + (unsigned)(p * 2) * 16 + poff16;
#pragma unroll
            for (int m = 0; m < 8; ++m) {
                unsigned a0, a1, a2, a3;
                ldsm4(abase + m * 256, a0, a1, a2, a3);
                mma16816(acc[m][0], a0, a1, a2, a3, bh0.x, bh0.y);
                mma16816(acc[m][1], a0, a1, a2, a3, bh1.x, bh1.y);
            }
        }
        // tail kx = 4, k8; ldmatrix.x4 covers 2 m-tiles (a0,a1 for m, m+1)
        {
            unsigned bt0 = *reinterpret_cast<const unsigned*>(
                smem + SBT + ((ky * 2 + 0) * 32 + lane) * 4);
            unsigned bt1 = *reinterpret_cast<const unsigned*>(
                smem + SBT + ((ky * 2 + 1) * 32 + lane) * 4);
            const unsigned abase = rowb + 4 * 16 + poff8;
#pragma unroll
            for (int mm = 0; mm < 4; ++mm) {
                unsigned r0, r1, r2, r3;
                ldsm4(abase + mm * 512, r0, r1, r2, r3);
                mma16808(acc[2 * mm][0],     r0, r1, bt0);
                mma16808(acc[2 * mm][1],     r0, r1, bt1);
                mma16808(acc[2 * mm + 1][0], r2, r3, bt0);
                mma16808(acc[2 * mm + 1][1], r2, r3, bt1);
            }
        }
    }

    // ---- store: c0=(px g, oc 2t), c1=(g,2t+1), c2=(g+8,2t), c3=(g+8,2t+1) ----
    const int g = lane >> 2;
    const int oy = y0 + r;
    if (oy < OH) {
#pragma unroll 1
        for (int m = 0; m < 8; ++m) {
            int ox0 = x0 + m * 16 + g;       // <= 503+... always < 508
            int ox1 = ox0 + 8;               // may reach 511 -> guard
#pragma unroll
            for (int h = 0; h < 2; ++h) {
                int oc0 = h * 8 + 2 * t;
                size_t base0 = (((size_t)b * 16 + oc0) * OH + oy) * OW;
                size_t base1 = base0 + (size_t)OH * OW;
                out[base0 + ox0] = acc[m][h][0];
                out[base1 + ox0] = acc[m][h][1];
                if (ox1 < OW) {
                    out[base0 + ox1] = acc[m][h][2];
                    out[base1 + ox1] = acc[m][h][3];
                }
            }
        }
    }
}

extern "C" void kernel_launch(void* const* d_in, const int* in_sizes, int n_in,
                              void* d_out, int out_size)
{
    const float* x    = (const float*)d_in[0];  // [32,6,512,512]
    const float* wgt  = (const float*)d_in[1];  // [16,6,5,5]
    const float* bias = (const float*)d_in[2];  // [16]
    float* out = (float*)d_out;                 // [32,16,508,508]

    dim3 grid((OW + TW - 1) / TW,    // 4
              (OH + TH - 1) / TH,    // 64
              32);                   // batch
    c3_hmma<<<grid, 256>>>(x, wgt, bias, out);
}

// round 10
// speedup vs baseline: 1.9993x; 1.9993x over previous
#include <cuda_runtime.h>
#include <cuda_fp16.h>

// C3 sparse-connectivity conv via fp16 mma.sync (f32 accum).
// x: [32,6,512,512] f32, weight: [16,6,5,5] f32, bias: [16] f32
// out: [32,16,508,508] f32
//
// CTA = 64 px (x) * 8 output rows (y) * 16 oc, one batch image. Warp = 1 row.
// Per kx: vertical tap-pairs (ky=0,1),(2,3) as m16n8k16 (k-lo = ky, k-hi =
// ky+1 -> A fragment hi regs are just +PW*16 bytes in the channels-last
// patch), ky=4 tail as m16n8k8. All A loads are plain conflict-free LDS.32.
// Small tile + 32-reg accumulators -> 3 CTAs/SM (24 warps) for latency hiding.

#define OW 508
#define OH 508
#define IW 512
#define IH 512
#define TW 64
#define TH 8
#define PW 68             // TW + 4
#define PH 12             // TH + 4
#define PLANE (IH * IW)

// smem layout (bytes)
#define SA     0                        // patch [PH][PW] x 16B = 13056
#define SB16   13056                    // [kx][p][half][n][t] uint2 = 5*2*2*32*8 = 6400
#define SBT    19456                    // [kx][half][n][t] u32 = 5*2*32*4 = 1280
#define SBIAS  20736                    // 16 f32
#define SMEM_TOTAL 20800

__constant__ unsigned CONN[16] = {
    0x07, 0x0E, 0x1C, 0x38, 0x31, 0x23, 0x0F, 0x1E,
    0x3C, 0x39, 0x33, 0x27, 0x1B, 0x36, 0x2D, 0x3F};

__device__ __forceinline__ unsigned pack_h2(float a, float b) {
    __half2 h = __floats2half2_rn(a, b);
    return *reinterpret_cast<unsigned*>(&h);
}
__device__ __forceinline__ void mma16816(float* c, unsigned a0, unsigned a1,
                                         unsigned a2, unsigned a3,
                                         unsigned b0, unsigned b1) {
    asm volatile(
        "mma.sync.aligned.m16n8k16.row.col.f32.f16.f16.f32 "
        "{%0,%1,%2,%3}, {%4,%5,%6,%7}, {%8,%9}, {%0,%1,%2,%3};"
        : "+f"(c[0]), "+f"(c[1]), "+f"(c[2]), "+f"(c[3])
        : "r"(a0), "r"(a1), "r"(a2), "r"(a3), "r"(b0), "r"(b1));
}
__device__ __forceinline__ void mma16808(float* c, unsigned a0, unsigned a1,
                                         unsigned b0) {
    asm volatile(
        "mma.sync.aligned.m16n8k8.row.col.f32.f16.f16.f32 "
        "{%0,%1,%2,%3}, {%4,%5}, {%6}, {%0,%1,%2,%3};"
        : "+f"(c[0]), "+f"(c[1]), "+f"(c[2]), "+f"(c[3])
        : "r"(a0), "r"(a1), "r"(b0));
}

__global__ void __launch_bounds__(256, 3)
c3_hmma(const float* __restrict__ x,
        const float* __restrict__ wgt,
        const float* __restrict__ bias,
        float* __restrict__ out)
{
    __shared__ __align__(16) char smem[SMEM_TOTAL];

    const int tid = threadIdx.x;
    const int x0 = blockIdx.x * TW;
    const int y0 = blockIdx.y * TH;
    const int b  = blockIdx.z;

    // ---- channels-last fp16 patch: [row][px][ic0..5, 0, 0] ----
    const float* xb = x + (size_t)b * 6 * PLANE;
    for (int i = tid; i < PH * PW; i += 256) {
        int row = i / PW, col = i % PW;
        int gy = y0 + row, gx = x0 + col;
        uint4 v = make_uint4(0u, 0u, 0u, 0u);
        if (gy < IH && gx < IW) {
            const float* p = xb + (size_t)gy * IW + gx;
            v.x = pack_h2(p[0],         p[PLANE]);
            v.y = pack_h2(p[2 * PLANE], p[3 * PLANE]);
            v.z = pack_h2(p[4 * PLANE], p[5 * PLANE]);
        }
        *reinterpret_cast<uint4*>(smem + SA + i * 16) = v;
    }
    // ---- k16 B tiles (vertical ky pairs): [kx][p][half][n][t] uint2 ----
    // b.x = {w[ic=2t], w[2t+1]} @ ky=2p ; b.y = same @ ky=2p+1
    for (int i = tid; i < 640; i += 256) {
        int t    = i & 3;
        int n    = (i >> 2) & 7;
        int half = (i >> 5) & 1;
        int p    = (i >> 6) & 1;
        int kx   = i >> 7;
        int oc = half * 8 + n;
        unsigned m = CONN[oc];
        uint2 w = make_uint2(0u, 0u);
        if (t < 3) {
            int ia = 2 * t, ib = 2 * t + 1;
            const float* wp = wgt + oc * 150;   // [ic][ky][kx], 25 per ic
            float la = (m & (1u << ia)) ? wp[ia * 25 + (2 * p) * 5 + kx] : 0.f;
            float lb = (m & (1u << ib)) ? wp[ib * 25 + (2 * p) * 5 + kx] : 0.f;
            float ha = (m & (1u << ia)) ? wp[ia * 25 + (2 * p + 1) * 5 + kx] : 0.f;
            float hb = (m & (1u << ib)) ? wp[ib * 25 + (2 * p + 1) * 5 + kx] : 0.f;
            w.x = pack_h2(la, lb);
            w.y = pack_h2(ha, hb);
        }
        *reinterpret_cast<uint2*>(smem + SB16 + i * 8) = w;
    }
    // ---- tail (ky=4) B tiles: [kx][half][n][t] u32 ----
    for (int i = tid; i < 320; i += 256) {
        int t    = i & 3;
        int n    = (i >> 2) & 7;
        int half = (i >> 5) & 1;
        int kx   = i >> 6;
        int oc = half * 8 + n;
        unsigned m = CONN[oc];
        unsigned w = 0u;
        if (t < 3) {
            int ia = 2 * t, ib = 2 * t + 1;
            const float* wp = wgt + oc * 150;
            float a = (m & (1u << ia)) ? wp[ia * 25 + 4 * 5 + kx] : 0.f;
            float c = (m & (1u << ib)) ? wp[ib * 25 + 4 * 5 + kx] : 0.f;
            w = pack_h2(a, c);
        }
        *reinterpret_cast<unsigned*>(smem + SBT + i * 4) = w;
    }
    if (tid < 16)
        reinterpret_cast<float*>(smem + SBIAS)[tid] = bias[tid];
    __syncthreads();

    const int wid  = tid >> 5;
    const int lane = tid & 31;
    const int g = lane >> 2;     // 0..7: A row within 8 / output px offset
    const int t = lane & 3;      // 0..3: K pair index / oc pair
    const int r = wid;           // output row within tile

    // acc[m-tile(4)][oc-half(2)][c0..c3], init with bias
    float acc[4][2][4];
    {
        const float* bs = reinterpret_cast<const float*>(smem + SBIAS);
#pragma unroll
        for (int h = 0; h < 2; ++h) {
            float b0 = bs[h * 8 + 2 * t];
            float b1 = bs[h * 8 + 2 * t + 1];
#pragma unroll
            for (int m = 0; m < 4; ++m) {
                acc[m][h][0] = b0; acc[m][h][1] = b1;
                acc[m][h][2] = b0; acc[m][h][3] = b1;
            }
        }
    }

#pragma unroll 1
    for (int kx = 0; kx < 5; ++kx) {
        // thread's base byte offset within a patch row view
        const char* base0 = smem + SA + ((r + 0) * PW + kx) * 16 + g * 16 + t * 4;
#pragma unroll
        for (int p = 0; p < 2; ++p) {
            const char* bb = smem + SB16 + ((kx * 2 + p) * 2) * 256 + lane * 8;
            uint2 bh0 = *reinterpret_cast<const uint2*>(bb);
            uint2 bh1 = *reinterpret_cast<const uint2*>(bb + 256);
            const char* arow = base0 + (2 * p) * (PW * 16);   // ky = 2p
#pragma unroll
            for (int m = 0; m < 4; ++m) {
                const char* ap = arow + m * 256;              // 16 px per m-tile
                unsigned a0 = *reinterpret_cast<const unsigned*>(ap);
                unsigned a1 = *reinterpret_cast<const unsigned*>(ap + 128);
                unsigned a2 = *reinterpret_cast<const unsigned*>(ap + PW * 16);
                unsigned a3 = *reinterpret_cast<const unsigned*>(ap + PW * 16 + 128);
                mma16816(acc[m][0], a0, a1, a2, a3, bh0.x, bh0.y);
                mma16816(acc[m][1], a0, a1, a2, a3, bh1.x, bh1.y);
            }
        }
        // tail ky = 4 (k8)
        {
            const char* bb = smem + SBT + (kx * 2) * 128 + lane * 4;
            unsigned bt0 = *reinterpret_cast<const unsigned*>(bb);
            unsigned bt1 = *reinterpret_cast<const unsigned*>(bb + 128);
            const char* arow = base0 + 4 * (PW * 16);
#pragma unroll
            for (int m = 0; m < 4; ++m) {
                const char* ap = arow + m * 256;
                unsigned a0 = *reinterpret_cast<const unsigned*>(ap);
                unsigned a1 = *reinterpret_cast<const unsigned*>(ap + 128);
                mma16808(acc[m][0], a0, a1, bt0);
                mma16808(acc[m][1], a0, a1, bt1);
            }
        }
    }

    // ---- store: c0=(px g, oc 2t), c1=(g,2t+1), c2=(g+8,2t), c3=(g+8,2t+1) ----
    const int oy = y0 + r;
    if (oy < OH) {
#pragma unroll 1
        for (int m = 0; m < 4; ++m) {
            int ox0 = x0 + m * 16 + g;   // <= 503, always valid
            int ox1 = ox0 + 8;           // may reach 511 -> guard
#pragma unroll
            for (int h = 0; h < 2; ++h) {
                int oc0 = h * 8 + 2 * t;
                size_t base0 = (((size_t)b * 16 + oc0) * OH + oy) * OW;
                size_t base1 = base0 + (size_t)OH * OW;
                out[base0 + ox0] = acc[m][h][0];
                out[base1 + ox0] = acc[m][h][1];
                if (ox1 < OW) {
                    out[base0 + ox1] = acc[m][h][2];
                    out[base1 + ox1] = acc[m][h][3];
                }
            }
        }
    }
}

extern "C" void kernel_launch(void* const* d_in, const int* in_sizes, int n_in,
                              void* d_out, int out_size)
{
    const float* x    = (const float*)d_in[0];  // [32,6,512,512]
    const float* wgt  = (const float*)d_in[1];  // [16,6,5,5]
    const float* bias = (const float*)d_in[2];  // [16]
    float* out = (float*)d_out;                 // [32,16,508,508]

    dim3 grid((OW + TW - 1) / TW,    // 8
              (OH + TH - 1) / TH,    // 64
              32);                   // batch
    c3_hmma<<<grid, 256>>>(x, wgt, bias, out);
}